// round 1
// baseline (speedup 1.0000x reference)
#include <cuda_runtime.h>

// Loss_60567628808292: YOLO loss (bugs faithfully reproduced).
// pred, target: [batch, 7, 7, 30] float32 flattened; M = batch*49 rows of 30.
// out: scalar float32 = bbox_loss + noobj_loss.

#define NCH 30
#define SDIM 7.0f
#define L_COORD 5.0f
#define L_NOOBJ 0.5f
#define MAX_ACTIVE 49   /* S*S */

// ---------------------------------------------------------------------------
// Kernel 1: no-object confidence loss over all rows.
// noobj rows: target[:,4] <= 0. Term: (p4-t4)^2 + (p9-t9)^2, scaled by 0.5.
// ---------------------------------------------------------------------------
__global__ void noobj_kernel(const float* __restrict__ pred,
                             const float* __restrict__ tgt,
                             int M, float* __restrict__ out) {
    float acc = 0.0f;
    const int stride = gridDim.x * blockDim.x;
    for (int r = blockIdx.x * blockDim.x + threadIdx.x; r < M; r += stride) {
        const size_t base = (size_t)r * NCH;
        const float t4 = __ldg(tgt + base + 4);
        if (!(t4 > 0.0f)) {
            const float t9 = __ldg(tgt + base + 9);
            const float p4 = __ldg(pred + base + 4);
            const float p9 = __ldg(pred + base + 9);
            const float d0 = p4 - t4;
            const float d1 = p9 - t9;
            acc += d0 * d0 + d1 * d1;
        }
    }
    // warp reduce
    #pragma unroll
    for (int off = 16; off > 0; off >>= 1)
        acc += __shfl_xor_sync(0xffffffffu, acc, off);

    __shared__ float warp_sums[32];
    const int lane = threadIdx.x & 31;
    const int wid = threadIdx.x >> 5;
    if (lane == 0) warp_sums[wid] = acc;
    __syncthreads();
    if (wid == 0) {
        const int nwarps = (blockDim.x + 31) >> 5;
        float v = (lane < nwarps) ? warp_sums[lane] : 0.0f;
        #pragma unroll
        for (int off = 16; off > 0; off >>= 1)
            v += __shfl_xor_sync(0xffffffffu, v, off);
        if (lane == 0) atomicAdd(out, L_NOOBJ * v);
    }
}

// ---------------------------------------------------------------------------
// Per-row, per-box "tot" value (l1+l2+l3+iou) and iou, reproducing the
// reference's buggy transform: x1 = x/7 - w/2 ; x2 = x1/7 + w/2.
// ---------------------------------------------------------------------------
__device__ __forceinline__ float box_tot(const float* __restrict__ pb,
                                         const float* __restrict__ tb,
                                         float& iou) {
    const float inv7 = 1.0f / SDIM;

    const float px = pb[0], py = pb[1], pw = pb[2], ph = pb[3], pc = pb[4];
    const float tx = tb[0], ty = tb[1], tw = tb[2], th = tb[3], tc = tb[4];

    const float px1 = px * inv7 - 0.5f * pw;
    const float py1 = py * inv7 - 0.5f * ph;
    const float px2 = px1 * inv7 + 0.5f * pw;   // uses NEW xy (original bug)
    const float py2 = py1 * inv7 + 0.5f * ph;

    const float tx1 = tx * inv7 - 0.5f * tw;
    const float ty1 = ty * inv7 - 0.5f * th;
    const float tx2 = tx1 * inv7 + 0.5f * tw;
    const float ty2 = ty1 * inv7 + 0.5f * th;

    const float dx1 = tx1 - px1, dy1 = ty1 - py1;
    const float l1 = L_COORD * dx1 * dx1 + dy1 * dy1;   // lambda only on x (bug)

    const float sx = sqrtf(tx2) - sqrtf(px2);
    const float sy = sqrtf(ty2) - sqrtf(py2);
    const float l2 = L_COORD * sx * sx + sy * sy;       // lambda only on x (bug)

    const float dc = tc - pc;
    const float l3 = dc * dc;

    const float ltx = fmaxf(px1, tx1), lty = fmaxf(py1, ty1);
    const float rbx = fminf(px2, tx2), rby = fminf(py2, ty2);
    const float wx = fmaxf(rbx - ltx, 0.0f);
    const float wy = fmaxf(rby - lty, 0.0f);
    const float inter = wx * wy;
    const float ap = (px2 - px1) * (py2 - py1);
    const float at = (tx2 - tx1) * (ty2 - ty1);
    iou = inter / (ap + at - inter);

    return l1 + l2 + l3 + iou;   // IoU itself added (bug)
}

// ---------------------------------------------------------------------------
// Kernel 2: bbox loss. Only the first MAX_ACTIVE obj rows (global flatten
// order) contribute. Single block scans rows from 0 with ballot-based
// global-rank computation; stops once MAX_ACTIVE obj rows seen.
// ---------------------------------------------------------------------------
#define BBOX_THREADS 256

__global__ void bbox_kernel(const float* __restrict__ pred,
                            const float* __restrict__ tgt,
                            int M, float* __restrict__ out) {
    __shared__ float s_acc;
    __shared__ int s_count;
    __shared__ int s_warp_cnt[BBOX_THREADS / 32];

    const int tid = threadIdx.x;
    const int lane = tid & 31;
    const int w = tid >> 5;
    const int nwarps = BBOX_THREADS / 32;

    if (tid == 0) { s_acc = 0.0f; s_count = 0; }
    __syncthreads();

    for (int base = 0; base < M; base += BBOX_THREADS) {
        const int r = base + tid;
        bool obj = false;
        if (r < M) obj = tgt[(size_t)r * NCH + 4] > 0.0f;

        const unsigned mask = __ballot_sync(0xffffffffu, obj);
        if (lane == 0) s_warp_cnt[w] = __popc(mask);
        __syncthreads();

        int before = 0, total = 0;
        #pragma unroll
        for (int j = 0; j < nwarps; j++) {
            const int c = s_warp_cnt[j];
            if (j < w) before += c;
            total += c;
        }
        const int rank = s_count + before + __popc(mask & ((1u << lane) - 1u));

        if (obj && rank < MAX_ACTIVE) {
            const float* p = pred + (size_t)r * NCH;
            const float* t = tgt + (size_t)r * NCH;
            float iou0, iou1;
            const float tot0 = box_tot(p,     t,     iou0);
            const float tot1 = box_tot(p + 5, t + 5, iou1);
            // jnp.argmax: first index on ties -> box 1 only if strictly greater
            const float sel = (iou1 > iou0) ? tot1 : tot0;
            atomicAdd(&s_acc, sel);
        }
        __syncthreads();           // everyone done reading s_count
        if (tid == 0) s_count += total;
        __syncthreads();
        if (s_count >= MAX_ACTIVE) break;
    }

    if (tid == 0) atomicAdd(out, s_acc);
}

// ---------------------------------------------------------------------------
extern "C" void kernel_launch(void* const* d_in, const int* in_sizes, int n_in,
                              void* d_out, int out_size) {
    const float* pred = (const float*)d_in[0];
    const float* tgt  = (const float*)d_in[1];
    float* out = (float*)d_out;

    const int M = in_sizes[0] / NCH;

    cudaMemsetAsync(out, 0, (size_t)out_size * sizeof(float), 0);

    const int threads = 256;
    int blocks = (M + threads - 1) / threads;
    if (blocks > 16384) blocks = 16384;
    noobj_kernel<<<blocks, threads>>>(pred, tgt, M, out);
    bbox_kernel<<<1, BBOX_THREADS>>>(pred, tgt, M, out);
}

// round 2
// speedup vs baseline: 1.0792x; 1.0792x over previous
#include <cuda_runtime.h>

// Loss_60567628808292: YOLO loss (bugs faithfully reproduced), fully fused.
// pred, target: [batch, 7, 7, 30] float32; M = batch*49 rows of 30 floats.
// out: scalar float32 = bbox_loss + noobj_loss.

#define NCH 30
#define SDIM 7.0f
#define L_COORD 5.0f
#define L_NOOBJ 0.5f
#define MAX_ACTIVE 49   /* S*S */
#define THREADS 256

// Cross-block accumulator + completion counter. Zero-initialized at load;
// the last block to finish writes out[] and resets both, so every graph
// replay sees the same initial state (deterministic).
__device__ float g_acc;
__device__ unsigned int g_done;

// ---------------------------------------------------------------------------
// Per-box "tot" value (l1+l2+l3+iou) and iou, reproducing the reference's
// buggy transform: x1 = x/7 - w/2 ; x2 = x1/7 + w/2 (uses the NEW xy).
// ---------------------------------------------------------------------------
__device__ __forceinline__ float box_tot(const float* __restrict__ pb,
                                         const float* __restrict__ tb,
                                         float& iou) {
    const float inv7 = 1.0f / SDIM;

    const float px = pb[0], py = pb[1], pw = pb[2], ph = pb[3], pc = pb[4];
    const float tx = tb[0], ty = tb[1], tw = tb[2], th = tb[3], tc = tb[4];

    const float px1 = px * inv7 - 0.5f * pw;
    const float py1 = py * inv7 - 0.5f * ph;
    const float px2 = px1 * inv7 + 0.5f * pw;   // original bug
    const float py2 = py1 * inv7 + 0.5f * ph;

    const float tx1 = tx * inv7 - 0.5f * tw;
    const float ty1 = ty * inv7 - 0.5f * th;
    const float tx2 = tx1 * inv7 + 0.5f * tw;
    const float ty2 = ty1 * inv7 + 0.5f * th;

    const float dx1 = tx1 - px1, dy1 = ty1 - py1;
    const float l1 = L_COORD * dx1 * dx1 + dy1 * dy1;   // lambda only on x (bug)

    const float sx = sqrtf(tx2) - sqrtf(px2);
    const float sy = sqrtf(ty2) - sqrtf(py2);
    const float l2 = L_COORD * sx * sx + sy * sy;       // lambda only on x (bug)

    const float dc = tc - pc;
    const float l3 = dc * dc;

    const float ltx = fmaxf(px1, tx1), lty = fmaxf(py1, ty1);
    const float rbx = fminf(px2, tx2), rby = fminf(py2, ty2);
    const float wx = fmaxf(rbx - ltx, 0.0f);
    const float wy = fmaxf(rby - lty, 0.0f);
    const float inter = wx * wy;
    const float ap = (px2 - px1) * (py2 - py1);
    const float at = (tx2 - tx1) * (ty2 - ty1);
    iou = inter / (ap + at - inter);

    return l1 + l2 + l3 + iou;   // IoU added into the selected loss (bug)
}

// ---------------------------------------------------------------------------
// Fused kernel.
//   block 0           : bbox loss (first MAX_ACTIVE obj rows in flatten order)
//   blocks 1..gridDim : no-object confidence loss (bulk memory phase)
// Last block to finish writes out[0] = g_acc and resets the globals.
// ---------------------------------------------------------------------------
__global__ void __launch_bounds__(THREADS)
yolo_loss_kernel(const float* __restrict__ pred,
                 const float* __restrict__ tgt,
                 int M, float* __restrict__ out) {
    const int tid = threadIdx.x;
    const int lane = tid & 31;
    const int w = tid >> 5;
    float partial = 0.0f;   // valid on tid==0 at the end

    if (blockIdx.x == 0) {
        // ---------------- bbox scan ----------------
        __shared__ float s_acc;
        __shared__ int s_count;
        __shared__ int s_warp_cnt[THREADS / 32];
        const int nwarps = THREADS / 32;

        if (tid == 0) { s_acc = 0.0f; s_count = 0; }
        __syncthreads();

        for (int base = 0; base < M; base += THREADS) {
            const int r = base + tid;
            bool obj = false;
            if (r < M) obj = tgt[(size_t)r * NCH + 4] > 0.0f;

            const unsigned mask = __ballot_sync(0xffffffffu, obj);
            if (lane == 0) s_warp_cnt[w] = __popc(mask);
            __syncthreads();

            int before = 0, total = 0;
            #pragma unroll
            for (int j = 0; j < nwarps; j++) {
                const int c = s_warp_cnt[j];
                if (j < w) before += c;
                total += c;
            }
            const int rank = s_count + before + __popc(mask & ((1u << lane) - 1u));

            if (obj && rank < MAX_ACTIVE) {
                const float* p = pred + (size_t)r * NCH;
                const float* t = tgt + (size_t)r * NCH;
                float iou0, iou1;
                const float tot0 = box_tot(p,     t,     iou0);
                const float tot1 = box_tot(p + 5, t + 5, iou1);
                // jnp.argmax: first index wins ties
                const float sel = (iou1 > iou0) ? tot1 : tot0;
                atomicAdd(&s_acc, sel);
            }
            __syncthreads();
            if (tid == 0) s_count += total;
            __syncthreads();
            if (s_count >= MAX_ACTIVE) break;
        }
        if (tid == 0) partial = s_acc;
    } else {
        // ---------------- noobj bulk phase ----------------
        // Rows r and r+T per thread; 8 independent float2 loads (all
        // unconditional -> max MLP, same DRAM sectors as scalar loads).
        const long long T = (long long)(gridDim.x - 1) * THREADS;
        const long long gid = (long long)(blockIdx.x - 1) * THREADS + tid;

        float acc = 0.0f;
        for (long long r = gid; r < M; r += 2 * T) {
            const long long r2 = r + T;
            const bool v2 = (r2 < (long long)M);
            const long long b1 = r * NCH;
            const long long b2 = v2 ? r2 * NCH : b1;

            const float2 t45a = *(const float2*)(tgt  + b1 + 4);
            const float2 t89a = *(const float2*)(tgt  + b1 + 8);
            const float2 p45a = *(const float2*)(pred + b1 + 4);
            const float2 p89a = *(const float2*)(pred + b1 + 8);
            const float2 t45b = *(const float2*)(tgt  + b2 + 4);
            const float2 t89b = *(const float2*)(tgt  + b2 + 8);
            const float2 p45b = *(const float2*)(pred + b2 + 4);
            const float2 p89b = *(const float2*)(pred + b2 + 8);

            {
                const float d0 = p45a.x - t45a.x;   // ch4
                const float d1 = p89a.y - t89a.y;   // ch9
                const float v = d0 * d0 + d1 * d1;
                if (!(t45a.x > 0.0f)) acc += v;
            }
            if (v2) {
                const float d0 = p45b.x - t45b.x;
                const float d1 = p89b.y - t89b.y;
                const float v = d0 * d0 + d1 * d1;
                if (!(t45b.x > 0.0f)) acc += v;
            }
        }
        acc *= L_NOOBJ;

        // warp + block reduce
        #pragma unroll
        for (int off = 16; off > 0; off >>= 1)
            acc += __shfl_xor_sync(0xffffffffu, acc, off);

        __shared__ float warp_sums[THREADS / 32];
        if (lane == 0) warp_sums[w] = acc;
        __syncthreads();
        if (w == 0) {
            float v = (lane < THREADS / 32) ? warp_sums[lane] : 0.0f;
            #pragma unroll
            for (int off = 16; off > 0; off >>= 1)
                v += __shfl_xor_sync(0xffffffffu, v, off);
            if (lane == 0) partial = v;
        }
    }

    // ---------------- completion protocol ----------------
    if (tid == 0) {
        atomicAdd(&g_acc, partial);
        __threadfence();
        const unsigned old = atomicAdd(&g_done, 1u);
        if (old == gridDim.x - 1) {
            // last block: publish and reset for the next graph replay
            out[0] = atomicExch(&g_acc, 0.0f);
            atomicExch(&g_done, 0u);
        }
    }
}

// ---------------------------------------------------------------------------
extern "C" void kernel_launch(void* const* d_in, const int* in_sizes, int n_in,
                              void* d_out, int out_size) {
    const float* pred = (const float*)d_in[0];
    const float* tgt  = (const float*)d_in[1];
    float* out = (float*)d_out;

    const int M = in_sizes[0] / NCH;

    // blocks 1..NB cover M rows at 2 rows/thread; +1 block for bbox
    int nb = (M + 2 * THREADS - 1) / (2 * THREADS);
    if (nb < 1) nb = 1;
    yolo_loss_kernel<<<nb + 1, THREADS>>>(pred, tgt, M, out);
}